// round 13
// baseline (speedup 1.0000x reference)
#include <cuda_runtime.h>
#include <cuda_fp16.h>
#include <cstdint>

// ---------------------------------------------------------------------------
// Problem constants
// ---------------------------------------------------------------------------
#define NTOK   8192
#define INDIM  4096
#define OUTDIM 4096
#define NE     8
#define RR     16
#define H4E    32
#define CAPACITY 3072          // int(3.0 * 8192 / 8)
#define ALPHA_ (1.0f/16.0f)
#define LN_EPS 1e-5f

// Main GEMM: pure K = 4096; lora rank-128 handled by separate RMW kernel
#define KT      128
#define LDT     40                 // fp16 smem row pad (halves): conflict-free ldmatrix
#define STAGEH  (2 * 128 * LDT)    // halves per stage (A+B) = 10240

// ---------------------------------------------------------------------------
// Device scratch (~4.2 MB total; large globals trip the mem guard)
// ---------------------------------------------------------------------------
__device__ __align__(1024) __half g_C2[NTOK * 128];     // gated lora coeffs (fp16)
__device__ __align__(1024) __half g_LBT[OUTDIM * 128];  // lora_B^T [o][j] (fp16)
__device__ int   g_topi[NTOK * 2];
__device__ float g_topg[NTOK * 2];
__device__ int   g_counts[16];          // [k][e]
__device__ int   g_ecount[NE];
__device__ int   g_elist[NE * 16384];
__device__ float g_ew[NE * 16384];

// ---------------------------------------------------------------------------
// PTX helpers
// ---------------------------------------------------------------------------
__device__ __forceinline__ uint32_t smem_u32(const void* p) {
    return (uint32_t)__cvta_generic_to_shared(p);
}
__device__ __forceinline__ void ldsm4(uint32_t& r0, uint32_t& r1,
                                      uint32_t& r2, uint32_t& r3, uint32_t addr) {
    asm volatile("ldmatrix.sync.aligned.m8n8.x4.shared.b16 {%0,%1,%2,%3}, [%4];"
                 : "=r"(r0), "=r"(r1), "=r"(r2), "=r"(r3) : "r"(addr));
}
__device__ __forceinline__ void mma16816(float* c, const uint32_t* a, const uint32_t* b) {
    asm volatile(
        "mma.sync.aligned.m16n8k16.row.col.f32.f16.f16.f32 "
        "{%0,%1,%2,%3}, {%4,%5,%6,%7}, {%8,%9}, {%0,%1,%2,%3};"
        : "+f"(c[0]), "+f"(c[1]), "+f"(c[2]), "+f"(c[3])
        : "r"(a[0]), "r"(a[1]), "r"(a[2]), "r"(a[3]), "r"(b[0]), "r"(b[1]));
}
__device__ __forceinline__ uint32_t packh2(float a, float b) {
    __half2 h = __floats2half2_rn(a, b);
    return *(uint32_t*)&h;
}

// ---------------------------------------------------------------------------
// Kernel: prep = counters zero + C2 zero + LBT smem-tiled transpose.
// ---------------------------------------------------------------------------
__global__ __launch_bounds__(256) void prep_kernel(const float* __restrict__ LB)
{
    const int b = blockIdx.x;
    const int t = threadIdx.x;
    if (b < 64) {
        __shared__ float sm[128][65];
        const int o0 = b * 64;
#pragma unroll
        for (int i = 0; i < 32; i++) {
            int idx = t + i * 256;
            int j   = idx >> 6;
            int oo  = idx & 63;
            sm[j][oo] = LB[(size_t)j * OUTDIM + o0 + oo];
        }
        __syncthreads();
#pragma unroll
        for (int i = 0; i < 32; i++) {
            int idx = t + i * 256;
            int oo  = idx >> 7;
            int j   = idx & 127;
            g_LBT[(size_t)(o0 + oo) * 128 + j] = __float2half_rn(sm[j][oo]);
        }
    } else {
        const int idx = (b - 64) * 256 + t;
        ((uint4*)g_C2)[idx] = make_uint4(0u, 0u, 0u, 0u);
        if (b == 64) {
            if (t < 16) g_counts[t] = 0;
            if (t < NE) g_ecount[t] = 0;
        }
    }
}

// ---------------------------------------------------------------------------
// Kernel: gate = Linear(4096->32) -> LN -> ReLU -> Linear(32->8) -> top2
// ---------------------------------------------------------------------------
__global__ __launch_bounds__(256) void gate_kernel(
    const float* __restrict__ x,
    const float* __restrict__ gw1, const float* __restrict__ gb1,
    const float* __restrict__ gamma, const float* __restrict__ beta,
    const float* __restrict__ gw2, const float* __restrict__ gb2)
{
    __shared__ float Xs[64][65];
    __shared__ float Wsh[64][33];
    __shared__ float Hs[64][33];

    const int tid = threadIdx.x;
    const int m0  = blockIdx.x * 64;
    const int mm  = tid & 63;
    const int jg  = tid >> 6;
    const int j0  = jg * 8;

    float acc[8];
#pragma unroll
    for (int jj = 0; jj < 8; jj++) acc[jj] = 0.f;

    for (int kc = 0; kc < 64; ++kc) {
        const int k0 = kc * 64;
#pragma unroll
        for (int i = 0; i < 4; i++) {
            int s  = tid + i * 256;
            int m  = s >> 4;
            int f4 = (s & 15) * 4;
            float4 v = *(const float4*)(x + (size_t)(m0 + m) * INDIM + k0 + f4);
            Xs[f4 + 0][m] = v.x; Xs[f4 + 1][m] = v.y;
            Xs[f4 + 2][m] = v.z; Xs[f4 + 3][m] = v.w;
        }
#pragma unroll
        for (int i = 0; i < 2; i++) {
            int s  = tid + i * 256;
            int j  = s >> 4;
            int f4 = (s & 15) * 4;
            float4 v = *(const float4*)(gw1 + (size_t)j * INDIM + k0 + f4);
            Wsh[f4 + 0][j] = v.x; Wsh[f4 + 1][j] = v.y;
            Wsh[f4 + 2][j] = v.z; Wsh[f4 + 3][j] = v.w;
        }
        __syncthreads();
#pragma unroll 16
        for (int kk = 0; kk < 64; ++kk) {
            float xv = Xs[kk][mm];
#pragma unroll
            for (int jj = 0; jj < 8; jj++) acc[jj] += xv * Wsh[kk][j0 + jj];
        }
        __syncthreads();
    }

#pragma unroll
    for (int jj = 0; jj < 8; jj++) Hs[mm][j0 + jj] = acc[jj];
    __syncthreads();

    if (tid < 64) {
        const int n = m0 + tid;
        float h[H4E];
        float mu = 0.f;
#pragma unroll
        for (int j = 0; j < H4E; j++) { h[j] = Hs[tid][j] + gb1[j]; mu += h[j]; }
        mu *= (1.0f / H4E);
        float var = 0.f;
#pragma unroll
        for (int j = 0; j < H4E; j++) { float d = h[j] - mu; var += d * d; }
        var *= (1.0f / H4E);
        const float inv = rsqrtf(var + LN_EPS);
#pragma unroll
        for (int j = 0; j < H4E; j++) {
            float v = (h[j] - mu) * inv * gamma[j] + beta[j];
            h[j] = fmaxf(v, 0.f);
        }
        float best = -3.4e38f, second = -3.4e38f;
        int be = 0, se = 0;
#pragma unroll
        for (int e = 0; e < NE; e++) {
            float g = gb2[e];
#pragma unroll
            for (int j = 0; j < H4E; j++) g += h[j] * gw2[e * H4E + j];
            if (g > best)        { second = best; se = be; best = g; be = e; }
            else if (g > second) { second = g; se = e; }
        }
        const float e1 = __expf(second - best);
        const float s  = 1.f + e1;
        g_topi[n * 2 + 0] = be;
        g_topi[n * 2 + 1] = se;
        g_topg[n * 2 + 0] = 1.f / s;
        g_topg[n * 2 + 1] = e1 / s;
        atomicAdd(&g_counts[be], 1);
        atomicAdd(&g_counts[8 + se], 1);
    }
}

// ---------------------------------------------------------------------------
// Kernel: route tokens into per-expert lists (capacity-filtered, ALPHA folded)
// ---------------------------------------------------------------------------
__global__ __launch_bounds__(256) void route_kernel()
{
    int n = blockIdx.x * 256 + threadIdx.x;
    if (n >= NTOK) return;
#pragma unroll
    for (int k = 0; k < 2; k++) {
        int e   = g_topi[n * 2 + k];
        float w = g_topg[n * 2 + k];
        if (g_counts[k * 8 + e] > CAPACITY) w = 0.f;
        if (w != 0.f) {
            int idx = atomicAdd(&g_ecount[e], 1);
            g_elist[e * 16384 + idx] = n;
            g_ew[e * 16384 + idx]    = w * ALPHA_;
        }
    }
}

// ---------------------------------------------------------------------------
// Kernel: coeff v3 -- K-split, 8 warps (proven 168us in R12).
// ---------------------------------------------------------------------------
__global__ __launch_bounds__(256) void coeff2_kernel(
    const float* __restrict__ x, const float* __restrict__ lA)
{
    __shared__ float Xs[4][32][65];
    __shared__ float As[4][32][16];
    __shared__ int   Ts[64];
    __shared__ float Wsc[64];

    const int e    = blockIdx.x;
    const int base = blockIdx.y * 64;
    const int cnt  = g_ecount[e];
    if (base >= cnt) return;
    const int tid = threadIdx.x;
    const int T   = min(64, cnt - base);

    if (tid < 64) {
        int i = min(tid, T - 1);
        Ts[tid]  = g_elist[e * 16384 + base + i];
        Wsc[tid] = g_ew[e * 16384 + base + i];
    }
    __syncthreads();

    const float* Ae = lA + (size_t)e * INDIM * RR;
    const int tok = tid & 63;
    const int kg  = tid >> 6;

    float acc[16];
#pragma unroll
    for (int r = 0; r < 16; r++) acc[r] = 0.f;

    float4 rx[8];
    float4 ra[2];

    auto ldg_cc = [&](int cc) {
#pragma unroll
        for (int i = 0; i < 8; i++) {
            int s    = tid + i * 256;
            int t8   = s >> 3;
            int tk   = t8 & 63;
            int kg_  = t8 >> 6;
            int kq   = s & 7;
            rx[i] = *(const float4*)(x + (size_t)Ts[tk] * INDIM
                                     + kg_ * 1024 + cc * 32 + kq * 4);
        }
#pragma unroll
        for (int i = 0; i < 2; i++) {
            int s    = tid + i * 256;
            int kg_  = s >> 7;
            int kk   = (s >> 2) & 31;
            int rq   = s & 3;
            ra[i] = *(const float4*)(Ae + (size_t)(kg_ * 1024 + cc * 32 + kk) * RR
                                     + rq * 4);
        }
    };

    auto sts_cc = [&]() {
#pragma unroll
        for (int i = 0; i < 8; i++) {
            int s   = tid + i * 256;
            int t8  = s >> 3;
            int tk  = t8 & 63;
            int kg_ = t8 >> 6;
            int kq  = s & 7;
            Xs[kg_][kq * 4 + 0][tk] = rx[i].x;
            Xs[kg_][kq * 4 + 1][tk] = rx[i].y;
            Xs[kg_][kq * 4 + 2][tk] = rx[i].z;
            Xs[kg_][kq * 4 + 3][tk] = rx[i].w;
        }
#pragma unroll
        for (int i = 0; i < 2; i++) {
            int s   = tid + i * 256;
            int kg_ = s >> 7;
            int kk  = (s >> 2) & 31;
            int rq  = s & 3;
            *(float4*)&As[kg_][kk][rq * 4] = ra[i];
        }
    };

    ldg_cc(0);
    for (int cc = 0; cc < 32; cc++) {
        __syncthreads();
        sts_cc();
        if (cc + 1 < 32) ldg_cc(cc + 1);
        __syncthreads();
#pragma unroll 8
        for (int kk = 0; kk < 32; kk++) {
            float xv = Xs[kg][kk][tok];
            float4 a0 = *(const float4*)&As[kg][kk][0];
            float4 a1 = *(const float4*)&As[kg][kk][4];
            float4 a2 = *(const float4*)&As[kg][kk][8];
            float4 a3 = *(const float4*)&As[kg][kk][12];
            acc[0]  += xv * a0.x; acc[1]  += xv * a0.y; acc[2]  += xv * a0.z; acc[3]  += xv * a0.w;
            acc[4]  += xv * a1.x; acc[5]  += xv * a1.y; acc[6]  += xv * a1.z; acc[7]  += xv * a1.w;
            acc[8]  += xv * a2.x; acc[9]  += xv * a2.y; acc[10] += xv * a2.z; acc[11] += xv * a2.w;
            acc[12] += xv * a3.x; acc[13] += xv * a3.y; acc[14] += xv * a3.z; acc[15] += xv * a3.w;
        }
    }

    __syncthreads();
    float* R = &Xs[0][0][0];
#pragma unroll
    for (int r = 0; r < 16; r++)
        R[(kg * 64 + tok) * 17 + r] = acc[r];
    __syncthreads();

    const int tk2 = tid >> 2;
    const int rq  = (tid & 3) * 4;
    if (tk2 < T) {
        float s0 = 0.f, s1 = 0.f, s2 = 0.f, s3 = 0.f;
#pragma unroll
        for (int g = 0; g < 4; g++) {
            const float* p = &R[(g * 64 + tk2) * 17 + rq];
            s0 += p[0]; s1 += p[1]; s2 += p[2]; s3 += p[3];
        }
        const float w = Wsc[tk2];
        __half* dst = g_C2 + (size_t)Ts[tk2] * 128 + e * RR + rq;
        dst[0] = __float2half_rn(w * s0);
        dst[1] = __float2half_rn(w * s1);
        dst[2] = __float2half_rn(w * s2);
        dst[3] = __float2half_rn(w * s3);
    }
}

// ---------------------------------------------------------------------------
// Kernel: main fp16 GEMM, pure K = 4096 (no lora dependency -> overlaps with
// the gate/route/coeff chain). BM=BN=128, 256 thr, 2 CTAs/SM. Proven in R10.
// ---------------------------------------------------------------------------
__global__ __launch_bounds__(256, 2) void gemm_kernel(
    const float* __restrict__ x, const float* __restrict__ W,
    float* __restrict__ out)
{
    __shared__ __align__(16) __half smem[2][STAGEH];

    const int tid  = threadIdx.x;
    const int lane = tid & 31;
    const int warp = tid >> 5;
    const int wm   = warp & 3;
    const int wn   = warp >> 2;

    const int b     = blockIdx.x;
    const int panel = b >> 9;
    const int r     = b & 511;
    const int m0    = (panel * 16 + (r & 15)) * 128;
    const int n0    = (r >> 4) * 128;

    float acc[2][8][4];
#pragma unroll
    for (int i = 0; i < 2; i++)
#pragma unroll
        for (int j = 0; j < 8; j++)
#pragma unroll
            for (int q = 0; q < 4; q++) acc[i][j][q] = 0.f;

    uint4 rs[4];

    auto ldg_stage = [&](int kt) {
        const int k0 = kt * 32;
#pragma unroll
        for (int i = 0; i < 4; i++) {
            int s2  = tid + i * 256;
            int row = s2 >> 3;
            int c   = (s2 & 7) * 4;
            float4 va = *(const float4*)(x + (size_t)(m0 + row) * INDIM + k0 + c);
            float4 vb = *(const float4*)(W + (size_t)(n0 + row) * INDIM + k0 + c);
            rs[i].x = packh2(va.x, va.y);
            rs[i].y = packh2(va.z, va.w);
            rs[i].z = packh2(vb.x, vb.y);
            rs[i].w = packh2(vb.z, vb.w);
        }
    };

    auto sts_stage = [&](int buf) {
        __half* As = smem[buf];
        __half* Bs = As + 128 * LDT;
#pragma unroll
        for (int i = 0; i < 4; i++) {
            int s2  = tid + i * 256;
            int row = s2 >> 3;
            int c   = (s2 & 7) * 4;
            *(uint2*)(As + row * LDT + c) = make_uint2(rs[i].x, rs[i].y);
            *(uint2*)(Bs + row * LDT + c) = make_uint2(rs[i].z, rs[i].w);
        }
    };

    ldg_stage(0);
    sts_stage(0);
    ldg_stage(1);

    for (int kt = 0; kt < KT; kt++) {
        __syncthreads();

        const uint32_t ab = smem_u32(smem[kt & 1]);
        const uint32_t bb = ab + 128 * LDT * 2;
#pragma unroll
        for (int step = 0; step < 2; step++) {
            const uint32_t abase = ab +
                ((wm * 32 + (lane & 15)) * LDT + step * 16 + (lane >> 4) * 8) * 2;
            const uint32_t bbase = bb +
                ((wn * 64 + (lane & 15)) * LDT + step * 16 + (lane >> 4) * 8) * 2;
            uint32_t A[2][4];
            uint32_t Bf[8][2];
#pragma unroll
            for (int i = 0; i < 2; i++)
                ldsm4(A[i][0], A[i][1], A[i][2], A[i][3], abase + i * 16 * LDT * 2);
#pragma unroll
            for (int j = 0; j < 4; j++) {
                uint32_t r0, r1, r2, r3;
                ldsm4(r0, r1, r2, r3, bbase + j * 16 * LDT * 2);
                Bf[2 * j][0] = r0; Bf[2 * j][1] = r2;
                Bf[2 * j + 1][0] = r1; Bf[2 * j + 1][1] = r3;
            }
#pragma unroll
            for (int i = 0; i < 2; i++)
#pragma unroll
                for (int j = 0; j < 8; j++)
                    mma16816(acc[i][j], A[i], Bf[j]);
        }

        if (kt + 1 < KT) sts_stage((kt + 1) & 1);
        if (kt + 2 < KT) ldg_stage(kt + 2);
    }

#pragma unroll
    for (int i = 0; i < 2; i++) {
        const int mrow = m0 + wm * 32 + i * 16 + (lane >> 2);
#pragma unroll
        for (int j = 0; j < 8; j++) {
            const int col = n0 + wn * 64 + j * 8 + (lane & 3) * 2;
            float2 v0 = make_float2(acc[i][j][0], acc[i][j][1]);
            float2 v1 = make_float2(acc[i][j][2], acc[i][j][3]);
            *(float2*)(out + (size_t)mrow * OUTDIM + col)       = v0;
            *(float2*)(out + (size_t)(mrow + 8) * OUTDIM + col) = v1;
        }
    }
}

// ---------------------------------------------------------------------------
// Kernel: rank-128 update  out += C2 @ LBT^T  (fp16 operands, RMW epilogue).
// Proven in R10.
// ---------------------------------------------------------------------------
__global__ __launch_bounds__(256, 2) void lora_kernel(float* __restrict__ out)
{
    __shared__ __align__(16) __half smem[2][STAGEH];

    const int tid  = threadIdx.x;
    const int lane = tid & 31;
    const int warp = tid >> 5;
    const int wm   = warp & 3;
    const int wn   = warp >> 2;

    const int b  = blockIdx.x;
    const int m0 = (b >> 5) * 128;
    const int n0 = (b & 31) * 128;

    float acc[2][8][4];
#pragma unroll
    for (int i = 0; i < 2; i++)
#pragma unroll
        for (int j = 0; j < 8; j++)
#pragma unroll
            for (int q = 0; q < 4; q++) acc[i][j][q] = 0.f;

    uint4 rs[4];

    auto ldg_stage = [&](int kt) {
        const int jb = kt * 32;
#pragma unroll
        for (int i = 0; i < 2; i++) {
            int s2  = tid + i * 256;
            int row = s2 >> 2;
            int c   = (s2 & 3) * 8;
            rs[i]     = *(const uint4*)(g_C2  + (size_t)(m0 + row) * 128 + jb + c);
            rs[2 + i] = *(const uint4*)(g_LBT + (size_t)(n0 + row) * 128 + jb + c);
        }
    };
    auto sts_stage = [&](int buf) {
        __half* As = smem[buf];
        __half* Bs = As + 128 * LDT;
#pragma unroll
        for (int i = 0; i < 2; i++) {
            int s2  = tid + i * 256;
            int row = s2 >> 2;
            int c   = (s2 & 3) * 8;
            *(uint4*)(As + row * LDT + c) = rs[i];
            *(uint4*)(Bs + row * LDT + c) = rs[2 + i];
        }
    };

    ldg_stage(0);
    sts_stage(0);

#pragma unroll
    for (int kt = 0; kt < 4; kt++) {
        __syncthreads();
        if (kt + 1 < 4) ldg_stage(kt + 1);

        const uint32_t ab = smem_u32(smem[kt & 1]);
        const uint32_t bb = ab + 128 * LDT * 2;
#pragma unroll
        for (int step = 0; step < 2; step++) {
            const uint32_t abase = ab +
                ((wm * 32 + (lane & 15)) * LDT + step * 16 + (lane >> 4) * 8) * 2;
            const uint32_t bbase = bb +
                ((wn * 64 + (lane & 15)) * LDT + step * 16 + (lane >> 4) * 8) * 2;
            uint32_t A[2][4];
            uint32_t Bf[8][2];
#pragma unroll
            for (int i = 0; i < 2; i++)
                ldsm4(A[i][0], A[i][1], A[i][2], A[i][3], abase + i * 16 * LDT * 2);
#pragma unroll
            for (int j = 0; j < 4; j++) {
                uint32_t r0, r1, r2, r3;
                ldsm4(r0, r1, r2, r3, bbase + j * 16 * LDT * 2);
                Bf[2 * j][0] = r0; Bf[2 * j][1] = r2;
                Bf[2 * j + 1][0] = r1; Bf[2 * j + 1][1] = r3;
            }
#pragma unroll
            for (int i = 0; i < 2; i++)
#pragma unroll
                for (int j = 0; j < 8; j++)
                    mma16816(acc[i][j], A[i], Bf[j]);
        }

        if (kt + 1 < 4) sts_stage((kt + 1) & 1);
    }

#pragma unroll
    for (int i = 0; i < 2; i++) {
        const int mrow = m0 + wm * 32 + i * 16 + (lane >> 2);
#pragma unroll
        for (int j = 0; j < 8; j++) {
            const int col = n0 + wn * 64 + j * 8 + (lane & 3) * 2;
            float2* p0 = (float2*)(out + (size_t)mrow * OUTDIM + col);
            float2* p1 = (float2*)(out + (size_t)(mrow + 8) * OUTDIM + col);
            float2 v0 = *p0, v1 = *p1;
            v0.x += acc[i][j][0]; v0.y += acc[i][j][1];
            v1.x += acc[i][j][2]; v1.y += acc[i][j][3];
            *p0 = v0; *p1 = v1;
        }
    }
}

// ---------------------------------------------------------------------------
// Host entry: fork-join DAG.
//   main stream: gemm_kernel (K=4096) ----------------------\
//   s2:          prep -> gate -> route -> coeff2 --- join ---+--> lora_kernel
// ---------------------------------------------------------------------------
extern "C" void kernel_launch(void* const* d_in, const int* in_sizes, int n_in,
                              void* d_out, int out_size)
{
    const float* x   = (const float*)d_in[0];
    const float* W   = (const float*)d_in[1];
    const float* lA  = (const float*)d_in[2];
    const float* lB  = (const float*)d_in[3];
    const float* gw1 = (const float*)d_in[4];
    const float* gb1 = (const float*)d_in[5];
    const float* gam = (const float*)d_in[6];
    const float* bet = (const float*)d_in[7];
    const float* gw2 = (const float*)d_in[8];
    const float* gb2 = (const float*)d_in[9];
    float* out = (float*)d_out;

    cudaStream_t s2;
    cudaEvent_t evFork, evJoin;
    cudaStreamCreateWithFlags(&s2, cudaStreamNonBlocking);
    cudaEventCreateWithFlags(&evFork, cudaEventDisableTiming);
    cudaEventCreateWithFlags(&evJoin, cudaEventDisableTiming);

    // fork: s2 branch depends on everything before this point on stream 0
    cudaEventRecord(evFork, 0);
    cudaStreamWaitEvent(s2, evFork, 0);

    prep_kernel<<<576, 256, 0, s2>>>(lB);
    gate_kernel<<<NTOK / 64, 256, 0, s2>>>(x, gw1, gb1, gam, bet, gw2, gb2);
    route_kernel<<<NTOK / 256, 256, 0, s2>>>();
    coeff2_kernel<<<dim3(NE, 256), 256, 0, s2>>>(x, lA);
    cudaEventRecord(evJoin, s2);

    // main GEMM runs concurrently with the s2 chain
    gemm_kernel<<<2048, 256>>>(x, W, out);

    // join: lora RMW needs coeff2 (s2) AND gemm (stream 0 program order)
    cudaStreamWaitEvent(0, evJoin, 0);
    lora_kernel<<<2048, 256>>>(out);

    cudaEventDestroy(evFork);
    cudaEventDestroy(evJoin);
    cudaStreamDestroy(s2);
}

// round 15
// speedup vs baseline: 1.1899x; 1.1899x over previous
#include <cuda_runtime.h>
#include <cuda_fp16.h>
#include <cstdint>

// ---------------------------------------------------------------------------
// Problem constants
// ---------------------------------------------------------------------------
#define NTOK   8192
#define INDIM  4096
#define OUTDIM 4096
#define NE     8
#define RR     16
#define H4E    32
#define CAPACITY 3072          // int(3.0 * 8192 / 8)
#define ALPHA_ (1.0f/16.0f)
#define LN_EPS 1e-5f

// Fused augmented-K GEMM: kts 0..3 = lora fp16 columns, 4..131 = fp32 main
#define KT      132
#define LORA_KT 4
#define LDT     40                 // fp16 smem row pad (halves): conflict-free ldmatrix
#define STAGEH  (2 * 128 * LDT)    // halves per stage (A+B) = 10240

// ---------------------------------------------------------------------------
// Device scratch (~4.2 MB total; large globals trip the mem guard)
// ---------------------------------------------------------------------------
__device__ __align__(1024) __half g_C2[NTOK * 128];     // gated lora coeffs (fp16)
__device__ __align__(1024) __half g_LBT[OUTDIM * 128];  // lora_B^T [o][j] (fp16)
__device__ int   g_topi[NTOK * 2];
__device__ float g_topg[NTOK * 2];
__device__ int   g_counts[16];          // [k][e]
__device__ int   g_ecount[NE];
__device__ int   g_elist[NE * 16384];
__device__ float g_ew[NE * 16384];

// ---------------------------------------------------------------------------
// PTX helpers
// ---------------------------------------------------------------------------
__device__ __forceinline__ uint32_t smem_u32(const void* p) {
    return (uint32_t)__cvta_generic_to_shared(p);
}
__device__ __forceinline__ void ldsm4(uint32_t& r0, uint32_t& r1,
                                      uint32_t& r2, uint32_t& r3, uint32_t addr) {
    asm volatile("ldmatrix.sync.aligned.m8n8.x4.shared.b16 {%0,%1,%2,%3}, [%4];"
                 : "=r"(r0), "=r"(r1), "=r"(r2), "=r"(r3) : "r"(addr));
}
__device__ __forceinline__ void mma16816(float* c, const uint32_t* a, const uint32_t* b) {
    asm volatile(
        "mma.sync.aligned.m16n8k16.row.col.f32.f16.f16.f32 "
        "{%0,%1,%2,%3}, {%4,%5,%6,%7}, {%8,%9}, {%0,%1,%2,%3};"
        : "+f"(c[0]), "+f"(c[1]), "+f"(c[2]), "+f"(c[3])
        : "r"(a[0]), "r"(a[1]), "r"(a[2]), "r"(a[3]), "r"(b[0]), "r"(b[1]));
}
__device__ __forceinline__ uint32_t packh2(float a, float b) {
    __half2 h = __floats2half2_rn(a, b);
    return *(uint32_t*)&h;
}

// ---------------------------------------------------------------------------
// Kernel 1: prep = counters zero + C2 zero + LBT smem-tiled transpose.
// ---------------------------------------------------------------------------
__global__ __launch_bounds__(256) void prep_kernel(const float* __restrict__ LB)
{
    const int b = blockIdx.x;
    const int t = threadIdx.x;
    if (b < 64) {
        __shared__ float sm[128][65];
        const int o0 = b * 64;
#pragma unroll
        for (int i = 0; i < 32; i++) {
            int idx = t + i * 256;
            int j   = idx >> 6;
            int oo  = idx & 63;
            sm[j][oo] = LB[(size_t)j * OUTDIM + o0 + oo];
        }
        __syncthreads();
#pragma unroll
        for (int i = 0; i < 32; i++) {
            int idx = t + i * 256;
            int oo  = idx >> 7;
            int j   = idx & 127;
            g_LBT[(size_t)(o0 + oo) * 128 + j] = __float2half_rn(sm[j][oo]);
        }
    } else {
        const int idx = (b - 64) * 256 + t;
        ((uint4*)g_C2)[idx] = make_uint4(0u, 0u, 0u, 0u);
        if (b == 64) {
            if (t < 16) g_counts[t] = 0;
            if (t < NE) g_ecount[t] = 0;
        }
    }
}

// ---------------------------------------------------------------------------
// Kernel 2: gate v2 -- register-tiled SIMT GEMM (32 tok x 32 j per block,
// 128 threads = 8 tm x 16 tj, each thread 4 tok x 2 j), then LN+ReLU+top2.
// Per kk: 1 LDS.128 (x, 4 tokens) + 1 LDS.64 (w, 2 j) + 8 FFMA.
// ---------------------------------------------------------------------------
__global__ __launch_bounds__(128) void gate_kernel(
    const float* __restrict__ x,
    const float* __restrict__ gw1, const float* __restrict__ gb1,
    const float* __restrict__ gamma, const float* __restrict__ beta,
    const float* __restrict__ gw2, const float* __restrict__ gb2)
{
    __shared__ float Xs[64][36];   // [kk][token pad36]
    __shared__ float Wsh[64][36];  // [kk][j pad36]
    __shared__ float Hs[32][33];   // [token][j]

    const int tid = threadIdx.x;
    const int m0  = blockIdx.x * 32;
    const int tm  = tid & 7;       // token group: tokens tm*4..+3
    const int tj  = tid >> 3;      // j group: j tj*2..+1

    float acc[4][2];
#pragma unroll
    for (int a = 0; a < 4; a++) { acc[a][0] = 0.f; acc[a][1] = 0.f; }

    for (int kc = 0; kc < 64; ++kc) {
        const int k0 = kc * 64;
        // x chunk: 32 tokens x 64 kk  (512 float4, 4 per thread)
#pragma unroll
        for (int i = 0; i < 4; i++) {
            int s  = tid + i * 128;
            int m  = s >> 4;
            int f4 = (s & 15) * 4;
            float4 v = *(const float4*)(x + (size_t)(m0 + m) * INDIM + k0 + f4);
            Xs[f4 + 0][m] = v.x; Xs[f4 + 1][m] = v.y;
            Xs[f4 + 2][m] = v.z; Xs[f4 + 3][m] = v.w;
        }
        // w chunk: 32 j x 64 kk
#pragma unroll
        for (int i = 0; i < 4; i++) {
            int s  = tid + i * 128;
            int j  = s >> 4;
            int f4 = (s & 15) * 4;
            float4 v = *(const float4*)(gw1 + (size_t)j * INDIM + k0 + f4);
            Wsh[f4 + 0][j] = v.x; Wsh[f4 + 1][j] = v.y;
            Wsh[f4 + 2][j] = v.z; Wsh[f4 + 3][j] = v.w;
        }
        __syncthreads();
#pragma unroll 8
        for (int kk = 0; kk < 64; ++kk) {
            float4 xv = *(const float4*)&Xs[kk][tm * 4];
            float2 wv = *(const float2*)&Wsh[kk][tj * 2];
            acc[0][0] += xv.x * wv.x; acc[0][1] += xv.x * wv.y;
            acc[1][0] += xv.y * wv.x; acc[1][1] += xv.y * wv.y;
            acc[2][0] += xv.z * wv.x; acc[2][1] += xv.z * wv.y;
            acc[3][0] += xv.w * wv.x; acc[3][1] += xv.w * wv.y;
        }
        __syncthreads();
    }

#pragma unroll
    for (int a = 0; a < 4; a++) {
        Hs[tm * 4 + a][tj * 2 + 0] = acc[a][0];
        Hs[tm * 4 + a][tj * 2 + 1] = acc[a][1];
    }
    __syncthreads();

    if (tid < 32) {
        const int n = m0 + tid;
        float h[H4E];
        float mu = 0.f;
#pragma unroll
        for (int j = 0; j < H4E; j++) { h[j] = Hs[tid][j] + gb1[j]; mu += h[j]; }
        mu *= (1.0f / H4E);
        float var = 0.f;
#pragma unroll
        for (int j = 0; j < H4E; j++) { float d = h[j] - mu; var += d * d; }
        var *= (1.0f / H4E);
        const float inv = rsqrtf(var + LN_EPS);
#pragma unroll
        for (int j = 0; j < H4E; j++) {
            float v = (h[j] - mu) * inv * gamma[j] + beta[j];
            h[j] = fmaxf(v, 0.f);
        }
        float best = -3.4e38f, second = -3.4e38f;
        int be = 0, se = 0;
#pragma unroll
        for (int e = 0; e < NE; e++) {
            float g = gb2[e];
#pragma unroll
            for (int j = 0; j < H4E; j++) g += h[j] * gw2[e * H4E + j];
            if (g > best)        { second = best; se = be; best = g; be = e; }
            else if (g > second) { second = g; se = e; }
        }
        const float e1 = __expf(second - best);
        const float s  = 1.f + e1;
        g_topi[n * 2 + 0] = be;
        g_topi[n * 2 + 1] = se;
        g_topg[n * 2 + 0] = 1.f / s;
        g_topg[n * 2 + 1] = e1 / s;
        atomicAdd(&g_counts[be], 1);
        atomicAdd(&g_counts[8 + se], 1);
    }
}

// ---------------------------------------------------------------------------
// Kernel 3: route tokens into per-expert lists (capacity-filtered, ALPHA folded)
// ---------------------------------------------------------------------------
__global__ __launch_bounds__(256) void route_kernel()
{
    int n = blockIdx.x * 256 + threadIdx.x;
    if (n >= NTOK) return;
#pragma unroll
    for (int k = 0; k < 2; k++) {
        int e   = g_topi[n * 2 + k];
        float w = g_topg[n * 2 + k];
        if (g_counts[k * 8 + e] > CAPACITY) w = 0.f;
        if (w != 0.f) {
            int idx = atomicAdd(&g_ecount[e], 1);
            g_elist[e * 16384 + idx] = n;
            g_ew[e * 16384 + idx]    = w * ALPHA_;
        }
    }
}

// ---------------------------------------------------------------------------
// Kernel 4 (PROFILED): coeff v3 -- K-split, 8 warps (proven 168us in R12).
// ---------------------------------------------------------------------------
__global__ __launch_bounds__(256) void coeff2_kernel(
    const float* __restrict__ x, const float* __restrict__ lA)
{
    __shared__ float Xs[4][32][65];
    __shared__ float As[4][32][16];
    __shared__ int   Ts[64];
    __shared__ float Wsc[64];

    const int e    = blockIdx.x;
    const int base = blockIdx.y * 64;
    const int cnt  = g_ecount[e];
    if (base >= cnt) return;
    const int tid = threadIdx.x;
    const int T   = min(64, cnt - base);

    if (tid < 64) {
        int i = min(tid, T - 1);
        Ts[tid]  = g_elist[e * 16384 + base + i];
        Wsc[tid] = g_ew[e * 16384 + base + i];
    }
    __syncthreads();

    const float* Ae = lA + (size_t)e * INDIM * RR;
    const int tok = tid & 63;
    const int kg  = tid >> 6;

    float acc[16];
#pragma unroll
    for (int r = 0; r < 16; r++) acc[r] = 0.f;

    float4 rx[8];
    float4 ra[2];

    auto ldg_cc = [&](int cc) {
#pragma unroll
        for (int i = 0; i < 8; i++) {
            int s    = tid + i * 256;
            int t8   = s >> 3;
            int tk   = t8 & 63;
            int kg_  = t8 >> 6;
            int kq   = s & 7;
            rx[i] = *(const float4*)(x + (size_t)Ts[tk] * INDIM
                                     + kg_ * 1024 + cc * 32 + kq * 4);
        }
#pragma unroll
        for (int i = 0; i < 2; i++) {
            int s    = tid + i * 256;
            int kg_  = s >> 7;
            int kk   = (s >> 2) & 31;
            int rq   = s & 3;
            ra[i] = *(const float4*)(Ae + (size_t)(kg_ * 1024 + cc * 32 + kk) * RR
                                     + rq * 4);
        }
    };

    auto sts_cc = [&]() {
#pragma unroll
        for (int i = 0; i < 8; i++) {
            int s   = tid + i * 256;
            int t8  = s >> 3;
            int tk  = t8 & 63;
            int kg_ = t8 >> 6;
            int kq  = s & 7;
            Xs[kg_][kq * 4 + 0][tk] = rx[i].x;
            Xs[kg_][kq * 4 + 1][tk] = rx[i].y;
            Xs[kg_][kq * 4 + 2][tk] = rx[i].z;
            Xs[kg_][kq * 4 + 3][tk] = rx[i].w;
        }
#pragma unroll
        for (int i = 0; i < 2; i++) {
            int s   = tid + i * 256;
            int kg_ = s >> 7;
            int kk  = (s >> 2) & 31;
            int rq  = s & 3;
            *(float4*)&As[kg_][kk][rq * 4] = ra[i];
        }
    };

    ldg_cc(0);
    for (int cc = 0; cc < 32; cc++) {
        __syncthreads();
        sts_cc();
        if (cc + 1 < 32) ldg_cc(cc + 1);
        __syncthreads();
#pragma unroll 8
        for (int kk = 0; kk < 32; kk++) {
            float xv = Xs[kg][kk][tok];
            float4 a0 = *(const float4*)&As[kg][kk][0];
            float4 a1 = *(const float4*)&As[kg][kk][4];
            float4 a2 = *(const float4*)&As[kg][kk][8];
            float4 a3 = *(const float4*)&As[kg][kk][12];
            acc[0]  += xv * a0.x; acc[1]  += xv * a0.y; acc[2]  += xv * a0.z; acc[3]  += xv * a0.w;
            acc[4]  += xv * a1.x; acc[5]  += xv * a1.y; acc[6]  += xv * a1.z; acc[7]  += xv * a1.w;
            acc[8]  += xv * a2.x; acc[9]  += xv * a2.y; acc[10] += xv * a2.z; acc[11] += xv * a2.w;
            acc[12] += xv * a3.x; acc[13] += xv * a3.y; acc[14] += xv * a3.z; acc[15] += xv * a3.w;
        }
    }

    __syncthreads();
    float* R = &Xs[0][0][0];
#pragma unroll
    for (int r = 0; r < 16; r++)
        R[(kg * 64 + tok) * 17 + r] = acc[r];
    __syncthreads();

    const int tk2 = tid >> 2;
    const int rq  = (tid & 3) * 4;
    if (tk2 < T) {
        float s0 = 0.f, s1 = 0.f, s2 = 0.f, s3 = 0.f;
#pragma unroll
        for (int g = 0; g < 4; g++) {
            const float* p = &R[(g * 64 + tk2) * 17 + rq];
            s0 += p[0]; s1 += p[1]; s2 += p[2]; s3 += p[3];
        }
        const float w = Wsc[tk2];
        __half* dst = g_C2 + (size_t)Ts[tk2] * 128 + e * RR + rq;
        dst[0] = __float2half_rn(w * s0);
        dst[1] = __float2half_rn(w * s1);
        dst[2] = __float2half_rn(w * s2);
        dst[3] = __float2half_rn(w * s3);
    }
}

// ---------------------------------------------------------------------------
// Kernel 5: fused fp16 mma.sync GEMM, augmented K = 4224 (lora kts 0..3).
// BM=BN=128, 256 threads, warp tile 32x64, 2 fp16 smem buffers, 2 CTAs/SM.
// (R12-proven configuration.)
// ---------------------------------------------------------------------------
__global__ __launch_bounds__(256, 2) void gemm_kernel(
    const float* __restrict__ x, const float* __restrict__ W,
    float* __restrict__ out)
{
    __shared__ __align__(16) __half smem[2][STAGEH];

    const int tid  = threadIdx.x;
    const int lane = tid & 31;
    const int warp = tid >> 5;
    const int wm   = warp & 3;
    const int wn   = warp >> 2;

    const int b     = blockIdx.x;
    const int panel = b >> 9;
    const int r     = b & 511;
    const int m0    = (panel * 16 + (r & 15)) * 128;
    const int n0    = (r >> 4) * 128;

    float acc[2][8][4];
#pragma unroll
    for (int i = 0; i < 2; i++)
#pragma unroll
        for (int j = 0; j < 8; j++)
#pragma unroll
            for (int q = 0; q < 4; q++) acc[i][j][q] = 0.f;

    uint4 rs[4];

    auto ldg_stage = [&](int kt) {
        if (kt < LORA_KT) {
            const int jb = kt * 32;
#pragma unroll
            for (int i = 0; i < 2; i++) {
                int s2  = tid + i * 256;
                int row = s2 >> 2;
                int c   = (s2 & 3) * 8;
                rs[i]     = *(const uint4*)(g_C2  + (size_t)(m0 + row) * 128 + jb + c);
                rs[2 + i] = *(const uint4*)(g_LBT + (size_t)(n0 + row) * 128 + jb + c);
            }
        } else {
            const int k0 = (kt - LORA_KT) * 32;
#pragma unroll
            for (int i = 0; i < 4; i++) {
                int s2  = tid + i * 256;
                int row = s2 >> 3;
                int c   = (s2 & 7) * 4;
                float4 va = *(const float4*)(x + (size_t)(m0 + row) * INDIM + k0 + c);
                float4 vb = *(const float4*)(W + (size_t)(n0 + row) * INDIM + k0 + c);
                rs[i].x = packh2(va.x, va.y);
                rs[i].y = packh2(va.z, va.w);
                rs[i].z = packh2(vb.x, vb.y);
                rs[i].w = packh2(vb.z, vb.w);
            }
        }
    };

    auto sts_stage = [&](int kt, int buf) {
        __half* As = smem[buf];
        __half* Bs = As + 128 * LDT;
        if (kt < LORA_KT) {
#pragma unroll
            for (int i = 0; i < 2; i++) {
                int s2  = tid + i * 256;
                int row = s2 >> 2;
                int c   = (s2 & 3) * 8;
                *(uint4*)(As + row * LDT + c) = rs[i];
                *(uint4*)(Bs + row * LDT + c) = rs[2 + i];
            }
        } else {
#pragma unroll
            for (int i = 0; i < 4; i++) {
                int s2  = tid + i * 256;
                int row = s2 >> 3;
                int c   = (s2 & 7) * 4;
                *(uint2*)(As + row * LDT + c) = make_uint2(rs[i].x, rs[i].y);
                *(uint2*)(Bs + row * LDT + c) = make_uint2(rs[i].z, rs[i].w);
            }
        }
    };

    ldg_stage(0);
    sts_stage(0, 0);
    ldg_stage(1);

    for (int kt = 0; kt < KT; kt++) {
        __syncthreads();

        const uint32_t ab = smem_u32(smem[kt & 1]);
        const uint32_t bb = ab + 128 * LDT * 2;
#pragma unroll
        for (int step = 0; step < 2; step++) {
            const uint32_t abase = ab +
                ((wm * 32 + (lane & 15)) * LDT + step * 16 + (lane >> 4) * 8) * 2;
            const uint32_t bbase = bb +
                ((wn * 64 + (lane & 15)) * LDT + step * 16 + (lane >> 4) * 8) * 2;
            uint32_t A[2][4];
            uint32_t Bf[8][2];
#pragma unroll
            for (int i = 0; i < 2; i++)
                ldsm4(A[i][0], A[i][1], A[i][2], A[i][3], abase + i * 16 * LDT * 2);
#pragma unroll
            for (int j = 0; j < 4; j++) {
                uint32_t r0, r1, r2, r3;
                ldsm4(r0, r1, r2, r3, bbase + j * 16 * LDT * 2);
                Bf[2 * j][0] = r0; Bf[2 * j][1] = r2;
                Bf[2 * j + 1][0] = r1; Bf[2 * j + 1][1] = r3;
            }
#pragma unroll
            for (int i = 0; i < 2; i++)
#pragma unroll
                for (int j = 0; j < 8; j++)
                    mma16816(acc[i][j], A[i], Bf[j]);
        }

        if (kt + 1 < KT) sts_stage(kt + 1, (kt + 1) & 1);
        if (kt + 2 < KT) ldg_stage(kt + 2);
    }

#pragma unroll
    for (int i = 0; i < 2; i++) {
        const int mrow = m0 + wm * 32 + i * 16 + (lane >> 2);
#pragma unroll
        for (int j = 0; j < 8; j++) {
            const int col = n0 + wn * 64 + j * 8 + (lane & 3) * 2;
            float2 v0 = make_float2(acc[i][j][0], acc[i][j][1]);
            float2 v1 = make_float2(acc[i][j][2], acc[i][j][3]);
            *(float2*)(out + (size_t)mrow * OUTDIM + col)       = v0;
            *(float2*)(out + (size_t)(mrow + 8) * OUTDIM + col) = v1;
        }
    }
}

// ---------------------------------------------------------------------------
// Host entry (serial -- R13 proved overlap hurts an L1/L2-bound GEMM)
// ---------------------------------------------------------------------------
extern "C" void kernel_launch(void* const* d_in, const int* in_sizes, int n_in,
                              void* d_out, int out_size)
{
    const float* x   = (const float*)d_in[0];
    const float* W   = (const float*)d_in[1];
    const float* lA  = (const float*)d_in[2];
    const float* lB  = (const float*)d_in[3];
    const float* gw1 = (const float*)d_in[4];
    const float* gb1 = (const float*)d_in[5];
    const float* gam = (const float*)d_in[6];
    const float* bet = (const float*)d_in[7];
    const float* gw2 = (const float*)d_in[8];
    const float* gb2 = (const float*)d_in[9];
    float* out = (float*)d_out;

    prep_kernel<<<576, 256>>>(lB);                                    // 1
    gate_kernel<<<NTOK / 32, 128>>>(x, gw1, gb1, gam, bet, gw2, gb2); // 2
    route_kernel<<<NTOK / 256, 256>>>();                              // 3
    coeff2_kernel<<<dim3(NE, 256), 256>>>(x, lA);                     // 4 <- profiled
    gemm_kernel<<<2048, 256>>>(x, W, out);                            // 5
}

// round 17
// speedup vs baseline: 1.2698x; 1.0671x over previous
#include <cuda_runtime.h>
#include <cuda_fp16.h>
#include <cstdint>

// ---------------------------------------------------------------------------
// Problem constants
// ---------------------------------------------------------------------------
#define NTOK   8192
#define INDIM  4096
#define OUTDIM 4096
#define NE     8
#define RR     16
#define H4E    32
#define CAPACITY 3072          // int(3.0 * 8192 / 8)
#define ALPHA_ (1.0f/16.0f)
#define LN_EPS 1e-5f

// Fused augmented-K GEMM: kts 0..3 = lora fp16 columns, 4..131 = fp32 main
#define KT      132
#define LORA_KT 4
#define LDT     40                 // fp16 smem row pad (halves): conflict-free ldmatrix
#define STAGEH  (2 * 128 * LDT)    // halves per stage (A+B) = 10240

// coeff2 dynamic smem layout (floats)
#define C2_XS    (8 * 32 * 33)     // 8448
#define C2_AS    (8 * 32 * 16)     // 4096
#define C2_TOT   (C2_XS + C2_AS + 64)          // 12608 floats
#define C2_SMEM  (C2_TOT * 4)                  // 50432 bytes

// ---------------------------------------------------------------------------
// Device scratch (~4.2 MB total; large globals trip the mem guard)
// ---------------------------------------------------------------------------
__device__ __align__(1024) __half g_C2[NTOK * 128];     // gated lora coeffs (fp16)
__device__ __align__(1024) __half g_LBT[OUTDIM * 128];  // lora_B^T [o][j] (fp16)
__device__ int   g_topi[NTOK * 2];
__device__ float g_topg[NTOK * 2];
__device__ int   g_counts[16];          // [k][e]
__device__ int   g_ecount[NE];
__device__ int   g_elist[NE * 16384];
__device__ float g_ew[NE * 16384];

// ---------------------------------------------------------------------------
// PTX helpers
// ---------------------------------------------------------------------------
__device__ __forceinline__ uint32_t smem_u32(const void* p) {
    return (uint32_t)__cvta_generic_to_shared(p);
}
__device__ __forceinline__ void ldsm4(uint32_t& r0, uint32_t& r1,
                                      uint32_t& r2, uint32_t& r3, uint32_t addr) {
    asm volatile("ldmatrix.sync.aligned.m8n8.x4.shared.b16 {%0,%1,%2,%3}, [%4];"
                 : "=r"(r0), "=r"(r1), "=r"(r2), "=r"(r3) : "r"(addr));
}
__device__ __forceinline__ void mma16816(float* c, const uint32_t* a, const uint32_t* b) {
    asm volatile(
        "mma.sync.aligned.m16n8k16.row.col.f32.f16.f16.f32 "
        "{%0,%1,%2,%3}, {%4,%5,%6,%7}, {%8,%9}, {%0,%1,%2,%3};"
        : "+f"(c[0]), "+f"(c[1]), "+f"(c[2]), "+f"(c[3])
        : "r"(a[0]), "r"(a[1]), "r"(a[2]), "r"(a[3]), "r"(b[0]), "r"(b[1]));
}
__device__ __forceinline__ uint32_t packh2(float a, float b) {
    __half2 h = __floats2half2_rn(a, b);
    return *(uint32_t*)&h;
}

// ---------------------------------------------------------------------------
// Kernel 1: prep = counters zero + C2 zero + LBT smem-tiled transpose.
// ---------------------------------------------------------------------------
__global__ __launch_bounds__(256) void prep_kernel(const float* __restrict__ LB)
{
    const int b = blockIdx.x;
    const int t = threadIdx.x;
    if (b < 64) {
        __shared__ float sm[128][65];
        const int o0 = b * 64;
#pragma unroll
        for (int i = 0; i < 32; i++) {
            int idx = t + i * 256;
            int j   = idx >> 6;
            int oo  = idx & 63;
            sm[j][oo] = LB[(size_t)j * OUTDIM + o0 + oo];
        }
        __syncthreads();
#pragma unroll
        for (int i = 0; i < 32; i++) {
            int idx = t + i * 256;
            int oo  = idx >> 7;
            int j   = idx & 127;
            g_LBT[(size_t)(o0 + oo) * 128 + j] = __float2half_rn(sm[j][oo]);
        }
    } else {
        const int idx = (b - 64) * 256 + t;
        ((uint4*)g_C2)[idx] = make_uint4(0u, 0u, 0u, 0u);
        if (b == 64) {
            if (t < 16) g_counts[t] = 0;
            if (t < NE) g_ecount[t] = 0;
        }
    }
}

// ---------------------------------------------------------------------------
// Kernel 2: gate v1 (R12-proven) = Linear -> LN -> ReLU -> Linear -> top2
// ---------------------------------------------------------------------------
__global__ __launch_bounds__(256) void gate_kernel(
    const float* __restrict__ x,
    const float* __restrict__ gw1, const float* __restrict__ gb1,
    const float* __restrict__ gamma, const float* __restrict__ beta,
    const float* __restrict__ gw2, const float* __restrict__ gb2)
{
    __shared__ float Xs[64][65];
    __shared__ float Wsh[64][33];
    __shared__ float Hs[64][33];

    const int tid = threadIdx.x;
    const int m0  = blockIdx.x * 64;
    const int mm  = tid & 63;
    const int jg  = tid >> 6;
    const int j0  = jg * 8;

    float acc[8];
#pragma unroll
    for (int jj = 0; jj < 8; jj++) acc[jj] = 0.f;

    for (int kc = 0; kc < 64; ++kc) {
        const int k0 = kc * 64;
#pragma unroll
        for (int i = 0; i < 4; i++) {
            int s  = tid + i * 256;
            int m  = s >> 4;
            int f4 = (s & 15) * 4;
            float4 v = *(const float4*)(x + (size_t)(m0 + m) * INDIM + k0 + f4);
            Xs[f4 + 0][m] = v.x; Xs[f4 + 1][m] = v.y;
            Xs[f4 + 2][m] = v.z; Xs[f4 + 3][m] = v.w;
        }
#pragma unroll
        for (int i = 0; i < 2; i++) {
            int s  = tid + i * 256;
            int j  = s >> 4;
            int f4 = (s & 15) * 4;
            float4 v = *(const float4*)(gw1 + (size_t)j * INDIM + k0 + f4);
            Wsh[f4 + 0][j] = v.x; Wsh[f4 + 1][j] = v.y;
            Wsh[f4 + 2][j] = v.z; Wsh[f4 + 3][j] = v.w;
        }
        __syncthreads();
#pragma unroll 16
        for (int kk = 0; kk < 64; ++kk) {
            float xv = Xs[kk][mm];
#pragma unroll
            for (int jj = 0; jj < 8; jj++) acc[jj] += xv * Wsh[kk][j0 + jj];
        }
        __syncthreads();
    }

#pragma unroll
    for (int jj = 0; jj < 8; jj++) Hs[mm][j0 + jj] = acc[jj];
    __syncthreads();

    if (tid < 64) {
        const int n = m0 + tid;
        float h[H4E];
        float mu = 0.f;
#pragma unroll
        for (int j = 0; j < H4E; j++) { h[j] = Hs[tid][j] + gb1[j]; mu += h[j]; }
        mu *= (1.0f / H4E);
        float var = 0.f;
#pragma unroll
        for (int j = 0; j < H4E; j++) { float d = h[j] - mu; var += d * d; }
        var *= (1.0f / H4E);
        const float inv = rsqrtf(var + LN_EPS);
#pragma unroll
        for (int j = 0; j < H4E; j++) {
            float v = (h[j] - mu) * inv * gamma[j] + beta[j];
            h[j] = fmaxf(v, 0.f);
        }
        float best = -3.4e38f, second = -3.4e38f;
        int be = 0, se = 0;
#pragma unroll
        for (int e = 0; e < NE; e++) {
            float g = gb2[e];
#pragma unroll
            for (int j = 0; j < H4E; j++) g += h[j] * gw2[e * H4E + j];
            if (g > best)        { second = best; se = be; best = g; be = e; }
            else if (g > second) { second = g; se = e; }
        }
        const float e1 = __expf(second - best);
        const float s  = 1.f + e1;
        g_topi[n * 2 + 0] = be;
        g_topi[n * 2 + 1] = se;
        g_topg[n * 2 + 0] = 1.f / s;
        g_topg[n * 2 + 1] = e1 / s;
        atomicAdd(&g_counts[be], 1);
        atomicAdd(&g_counts[8 + se], 1);
    }
}

// ---------------------------------------------------------------------------
// Kernel 3: route tokens into per-expert lists (capacity-filtered, ALPHA folded)
// ---------------------------------------------------------------------------
__global__ __launch_bounds__(256) void route_kernel()
{
    int n = blockIdx.x * 256 + threadIdx.x;
    if (n >= NTOK) return;
#pragma unroll
    for (int k = 0; k < 2; k++) {
        int e   = g_topi[n * 2 + k];
        float w = g_topg[n * 2 + k];
        if (g_counts[k * 8 + e] > CAPACITY) w = 0.f;
        if (w != 0.f) {
            int idx = atomicAdd(&g_ecount[e], 1);
            g_elist[e * 16384 + idx] = n;
            g_ew[e * 16384 + idx]    = w * ALPHA_;
        }
    }
}

// ---------------------------------------------------------------------------
// Kernel 4 (PROFILED): coeff v4 -- 32 tokens x 8 K-groups (512 wide each).
// 256 threads, grid (NE, 256), dynamic smem 50432 B (over the 48KB static
// limit -> extern + cudaFuncSetAttribute). cc loop: 16 iterations of 32 kk.
// ---------------------------------------------------------------------------
__global__ __launch_bounds__(256) void coeff2_kernel(
    const float* __restrict__ x, const float* __restrict__ lA)
{
    extern __shared__ float dsm[];
    float (*Xs)[32][33] = (float (*)[32][33])dsm;             // [8][32][33]
    float (*As)[32][16] = (float (*)[32][16])(dsm + C2_XS);   // [8][32][16]
    int*   Ts  = (int*)(dsm + C2_XS + C2_AS);
    float* Wsc = (float*)(dsm + C2_XS + C2_AS + 32);

    const int e    = blockIdx.x;
    const int base = blockIdx.y * 32;
    const int cnt  = g_ecount[e];
    if (base >= cnt) return;
    const int tid = threadIdx.x;
    const int T   = min(32, cnt - base);

    if (tid < 32) {
        int i = min(tid, T - 1);
        Ts[tid]  = g_elist[e * 16384 + base + i];
        Wsc[tid] = g_ew[e * 16384 + base + i];
    }
    __syncthreads();

    const float* Ae = lA + (size_t)e * INDIM * RR;
    const int tok = tid & 31;
    const int kg  = tid >> 5;          // 0..7, K range kg*512 .. +511

    float acc[16];
#pragma unroll
    for (int r = 0; r < 16; r++) acc[r] = 0.f;

    float4 rx[8];   // x staging: 2048 float4 slots / 256 thr
    float4 ra[4];   // A staging: 1024 float4 slots / 256 thr

    auto ldg_cc = [&](int cc) {
#pragma unroll
        for (int i = 0; i < 8; i++) {
            int s   = tid + i * 256;       // 0..2047
            int t8  = s >> 3;              // 0..255 = 32 tok x 8 kg
            int tk  = t8 & 31;
            int kg_ = t8 >> 5;
            int kq  = s & 7;
            rx[i] = *(const float4*)(x + (size_t)Ts[tk] * INDIM
                                     + kg_ * 512 + cc * 32 + kq * 4);
        }
#pragma unroll
        for (int i = 0; i < 4; i++) {
            int s   = tid + i * 256;       // 0..1023
            int kg_ = s >> 7;              // 0..7
            int kk  = (s >> 2) & 31;
            int rq  = s & 3;
            ra[i] = *(const float4*)(Ae + (size_t)(kg_ * 512 + cc * 32 + kk) * RR
                                     + rq * 4);
        }
    };

    auto sts_cc = [&]() {
#pragma unroll
        for (int i = 0; i < 8; i++) {
            int s   = tid + i * 256;
            int t8  = s >> 3;
            int tk  = t8 & 31;
            int kg_ = t8 >> 5;
            int kq  = s & 7;
            Xs[kg_][kq * 4 + 0][tk] = rx[i].x;
            Xs[kg_][kq * 4 + 1][tk] = rx[i].y;
            Xs[kg_][kq * 4 + 2][tk] = rx[i].z;
            Xs[kg_][kq * 4 + 3][tk] = rx[i].w;
        }
#pragma unroll
        for (int i = 0; i < 4; i++) {
            int s   = tid + i * 256;
            int kg_ = s >> 7;
            int kk  = (s >> 2) & 31;
            int rq  = s & 3;
            *(float4*)&As[kg_][kk][rq * 4] = ra[i];
        }
    };

    ldg_cc(0);
    for (int cc = 0; cc < 16; cc++) {
        __syncthreads();                // readers of previous chunk done
        sts_cc();
        if (cc + 1 < 16) ldg_cc(cc + 1);
        __syncthreads();                // chunk visible
#pragma unroll 8
        for (int kk = 0; kk < 32; kk++) {
            float xv = Xs[kg][kk][tok];
            float4 a0 = *(const float4*)&As[kg][kk][0];
            float4 a1 = *(const float4*)&As[kg][kk][4];
            float4 a2 = *(const float4*)&As[kg][kk][8];
            float4 a3 = *(const float4*)&As[kg][kk][12];
            acc[0]  += xv * a0.x; acc[1]  += xv * a0.y; acc[2]  += xv * a0.z; acc[3]  += xv * a0.w;
            acc[4]  += xv * a1.x; acc[5]  += xv * a1.y; acc[6]  += xv * a1.z; acc[7]  += xv * a1.w;
            acc[8]  += xv * a2.x; acc[9]  += xv * a2.y; acc[10] += xv * a2.z; acc[11] += xv * a2.w;
            acc[12] += xv * a3.x; acc[13] += xv * a3.y; acc[14] += xv * a3.z; acc[15] += xv * a3.w;
        }
    }

    // cross-kg reduction through smem: 256 rows x 17 = 4352 floats (< Xs span)
    __syncthreads();
    float* R = dsm;
#pragma unroll
    for (int r = 0; r < 16; r++)
        R[(kg * 32 + tok) * 17 + r] = acc[r];   // stride 17: conflict-free
    __syncthreads();

    // 32 tokens x 16 r = 512 items; thread -> (tok = tid>>3, r pair = (tid&7)*2)
    const int tk2 = tid >> 3;          // 0..31
    const int rp  = (tid & 7) * 2;     // 0,2,..,14
    if (tk2 < T) {
        float s0 = 0.f, s1 = 0.f;
#pragma unroll
        for (int g = 0; g < 8; g++) {
            const float* p = &R[(g * 32 + tk2) * 17 + rp];
            s0 += p[0]; s1 += p[1];
        }
        const float w = Wsc[tk2];
        __half* dst = g_C2 + (size_t)Ts[tk2] * 128 + e * RR + rp;
        dst[0] = __float2half_rn(w * s0);
        dst[1] = __float2half_rn(w * s1);
    }
}

// ---------------------------------------------------------------------------
// Kernel 5: fused fp16 mma.sync GEMM, augmented K = 4224 (R12-proven).
// ---------------------------------------------------------------------------
__global__ __launch_bounds__(256, 2) void gemm_kernel(
    const float* __restrict__ x, const float* __restrict__ W,
    float* __restrict__ out)
{
    __shared__ __align__(16) __half smem[2][STAGEH];

    const int tid  = threadIdx.x;
    const int lane = tid & 31;
    const int warp = tid >> 5;
    const int wm   = warp & 3;
    const int wn   = warp >> 2;

    const int b     = blockIdx.x;
    const int panel = b >> 9;
    const int r     = b & 511;
    const int m0    = (panel * 16 + (r & 15)) * 128;
    const int n0    = (r >> 4) * 128;

    float acc[2][8][4];
#pragma unroll
    for (int i = 0; i < 2; i++)
#pragma unroll
        for (int j = 0; j < 8; j++)
#pragma unroll
            for (int q = 0; q < 4; q++) acc[i][j][q] = 0.f;

    uint4 rs[4];

    auto ldg_stage = [&](int kt) {
        if (kt < LORA_KT) {
            const int jb = kt * 32;
#pragma unroll
            for (int i = 0; i < 2; i++) {
                int s2  = tid + i * 256;
                int row = s2 >> 2;
                int c   = (s2 & 3) * 8;
                rs[i]     = *(const uint4*)(g_C2  + (size_t)(m0 + row) * 128 + jb + c);
                rs[2 + i] = *(const uint4*)(g_LBT + (size_t)(n0 + row) * 128 + jb + c);
            }
        } else {
            const int k0 = (kt - LORA_KT) * 32;
#pragma unroll
            for (int i = 0; i < 4; i++) {
                int s2  = tid + i * 256;
                int row = s2 >> 3;
                int c   = (s2 & 7) * 4;
                float4 va = *(const float4*)(x + (size_t)(m0 + row) * INDIM + k0 + c);
                float4 vb = *(const float4*)(W + (size_t)(n0 + row) * INDIM + k0 + c);
                rs[i].x = packh2(va.x, va.y);
                rs[i].y = packh2(va.z, va.w);
                rs[i].z = packh2(vb.x, vb.y);
                rs[i].w = packh2(vb.z, vb.w);
            }
        }
    };

    auto sts_stage = [&](int kt, int buf) {
        __half* As = smem[buf];
        __half* Bs = As + 128 * LDT;
        if (kt < LORA_KT) {
#pragma unroll
            for (int i = 0; i < 2; i++) {
                int s2  = tid + i * 256;
                int row = s2 >> 2;
                int c   = (s2 & 3) * 8;
                *(uint4*)(As + row * LDT + c) = rs[i];
                *(uint4*)(Bs + row * LDT + c) = rs[2 + i];
            }
        } else {
#pragma unroll
            for (int i = 0; i < 4; i++) {
                int s2  = tid + i * 256;
                int row = s2 >> 3;
                int c   = (s2 & 7) * 4;
                *(uint2*)(As + row * LDT + c) = make_uint2(rs[i].x, rs[i].y);
                *(uint2*)(Bs + row * LDT + c) = make_uint2(rs[i].z, rs[i].w);
            }
        }
    };

    ldg_stage(0);
    sts_stage(0, 0);
    ldg_stage(1);

    for (int kt = 0; kt < KT; kt++) {
        __syncthreads();

        const uint32_t ab = smem_u32(smem[kt & 1]);
        const uint32_t bb = ab + 128 * LDT * 2;
#pragma unroll
        for (int step = 0; step < 2; step++) {
            const uint32_t abase = ab +
                ((wm * 32 + (lane & 15)) * LDT + step * 16 + (lane >> 4) * 8) * 2;
            const uint32_t bbase = bb +
                ((wn * 64 + (lane & 15)) * LDT + step * 16 + (lane >> 4) * 8) * 2;
            uint32_t A[2][4];
            uint32_t Bf[8][2];
#pragma unroll
            for (int i = 0; i < 2; i++)
                ldsm4(A[i][0], A[i][1], A[i][2], A[i][3], abase + i * 16 * LDT * 2);
#pragma unroll
            for (int j = 0; j < 4; j++) {
                uint32_t r0, r1, r2, r3;
                ldsm4(r0, r1, r2, r3, bbase + j * 16 * LDT * 2);
                Bf[2 * j][0] = r0; Bf[2 * j][1] = r2;
                Bf[2 * j + 1][0] = r1; Bf[2 * j + 1][1] = r3;
            }
#pragma unroll
            for (int i = 0; i < 2; i++)
#pragma unroll
                for (int j = 0; j < 8; j++)
                    mma16816(acc[i][j], A[i], Bf[j]);
        }

        if (kt + 1 < KT) sts_stage(kt + 1, (kt + 1) & 1);
        if (kt + 2 < KT) ldg_stage(kt + 2);
    }

#pragma unroll
    for (int i = 0; i < 2; i++) {
        const int mrow = m0 + wm * 32 + i * 16 + (lane >> 2);
#pragma unroll
        for (int j = 0; j < 8; j++) {
            const int col = n0 + wn * 64 + j * 8 + (lane & 3) * 2;
            float2 v0 = make_float2(acc[i][j][0], acc[i][j][1]);
            float2 v1 = make_float2(acc[i][j][2], acc[i][j][3]);
            *(float2*)(out + (size_t)mrow * OUTDIM + col)       = v0;
            *(float2*)(out + (size_t)(mrow + 8) * OUTDIM + col) = v1;
        }
    }
}

// ---------------------------------------------------------------------------
// Host entry (serial -- R13 proved overlap hurts an L1/L2-bound GEMM)
// ---------------------------------------------------------------------------
extern "C" void kernel_launch(void* const* d_in, const int* in_sizes, int n_in,
                              void* d_out, int out_size)
{
    const float* x   = (const float*)d_in[0];
    const float* W   = (const float*)d_in[1];
    const float* lA  = (const float*)d_in[2];
    const float* lB  = (const float*)d_in[3];
    const float* gw1 = (const float*)d_in[4];
    const float* gb1 = (const float*)d_in[5];
    const float* gam = (const float*)d_in[6];
    const float* bet = (const float*)d_in[7];
    const float* gw2 = (const float*)d_in[8];
    const float* gb2 = (const float*)d_in[9];
    float* out = (float*)d_out;

    cudaFuncSetAttribute(coeff2_kernel,
                         cudaFuncAttributeMaxDynamicSharedMemorySize, C2_SMEM);

    prep_kernel<<<576, 256>>>(lB);                                    // 1
    gate_kernel<<<NTOK / 64, 256>>>(x, gw1, gb1, gam, bet, gw2, gb2); // 2
    route_kernel<<<NTOK / 256, 256>>>();                              // 3
    coeff2_kernel<<<dim3(NE, 256), 256, C2_SMEM>>>(x, lA);            // 4 <- profiled
    gemm_kernel<<<2048, 256>>>(x, W, out);                            // 5
}